// round 17
// baseline (speedup 1.0000x reference)
#include <cuda_runtime.h>
#include <cstdint>

// S3FD anchor assignment — 2 kernels.
//   k_prep (489 blocks, spin grid-barrier; all blocks co-resident: 489 < 1 wave):
//     phase A: per-block smem hist + cellid (4 anchors/thread); blocks<NCELL also
//              build per-cell GT lists (ballot compaction, increasing GT order =
//              reference first-max tie-break); blocks<4 zero g_top.
//     ticket:  last-arriving block scans block counts in place (per-cell excl
//              prefix), bin offsets, total pairs P, equal-pair LPT worklist
//              (chunk ~ (P/1480)/cnt rounded up to x256, cap 1024), then
//              releases the flag.
//     phase B: all blocks spin on the flag, then scatter 4B anchor indices
//              (g_binned) using __ldcg (own L1 copy of blockhist is STALE after
//              the in-place scan). Final ticket resets barrier state for replay.
//   k_main (R14, frozen): LPT equal-pair chunks, templated unroll JM, IoU vs
//     cell GT list, per-lane-predicated exact __fdiv_rn, argmax (strict >,
//     first-max ties), per-GT ungated MAX slot (fake-seeded: monotone-max safe)
//     + 0.1-gated 3-slot cascade; last-finishing block resolves forced claims.
// Output dtype float32 (small ints as floats). All exact comparisons use
// __f*_rn-rounded iou: bit-identical to the float32 reference. The 0.1 gate is
// exact: cascade entries are only consumed under a vals>0.1 condition, and >0.5
// counting is unaffected since >0.5 entries form a prefix of the sorted row.

#define TPB 256
#define APT 4
#define CHUNK 1024             // prep chunk / max main chunk (= TPB*APT)
#define MAXM 256               // >= n_gt (200)
#define MAXN (1 << 20)         // >= n_anchor (500000)
#define NB_MAX (MAXN / CHUNK)
#define NCELL 256
#define GRIDW 16
#define CELL_PX 64.0f
#define EXPAND 65.0f           // 64 max anchor half-extent + 1px rounding slack
#define WCAP (NCELL + MAXN / 256 + 2)
#define TARGET_CHUNKS 1480     // ~2 balanced waves of main blocks

__device__ unsigned char g_cellid[MAXN];
__device__ int g_blockhist[NCELL * NB_MAX];
__device__ int g_offs[NCELL];
__device__ int g_nwork;
__device__ int4 g_work[WCAP];
__device__ int g_binned[MAXN];
__device__ int g_gtcnt[NCELL];
__device__ int g_gtlist[NCELL * MAXM];
// Per-gt: [4g+0] = ungated max slot, [4g+1..3] = 0.1-gated top-3 cascade.
__device__ unsigned long long g_top[MAXM * 4];
__device__ unsigned g_bar1, g_bar2, g_go;   // prep barrier state (self-resetting)
__device__ unsigned g_tick2;                // k_main ticket (self-resetting)

__device__ __forceinline__ void cascade_insert(unsigned long long* s, unsigned long long v) {
#pragma unroll
    for (int i = 0; i < 3; i++) {
        unsigned long long old = atomicMax(&s[i], v);
        v = old < v ? old : v;
        if (v == 0ull) return;
    }
}

__device__ __forceinline__ int cell_of(float4 a) {
    int cx = min(GRIDW - 1, max(0, (int)((a.x + a.z) * (0.5f / CELL_PX))));
    int cy = min(GRIDW - 1, max(0, (int)((a.y + a.w) * (0.5f / CELL_PX))));
    return cy * GRIDW + cx;
}

__global__ void __launch_bounds__(TPB) k_prep(
    const float4* __restrict__ anc, const float4* __restrict__ gts,
    int n, int m, int nb)
{
    __shared__ int h[NCELL];
    __shared__ int s1[NCELL];
    __shared__ int s2[NCELL];
    const int t = threadIdx.x, b = blockIdx.x;

    // ---------- phase A: histogram + cellid ----------
    h[t] = 0;
    __syncthreads();
    const int base = b * CHUNK;
#pragma unroll
    for (int k = 0; k < APT; k++) {
        int i = base + k * TPB + t;
        if (i < n) {
            int c = cell_of(anc[i]);
            g_cellid[i] = (unsigned char)c;
            atomicAdd(&h[c], 1);
        }
    }
    // Blocks < NCELL: per-cell GT list (order-preserving ballot compaction).
    if (b < NCELL) {
        if (b < 4) {
            int i = b * TPB + t;
            if (i < MAXM * 4) g_top[i] = 0ull;
        }
        float cx0 = (b & (GRIDW - 1)) * CELL_PX - EXPAND;
        float cx1 = (b & (GRIDW - 1)) * CELL_PX + CELL_PX + EXPAND;
        float cy0 = (b >> 4) * CELL_PX - EXPAND;
        float cy1 = (b >> 4) * CELL_PX + CELL_PX + EXPAND;
        bool p = false;
        if (t < m) {
            float4 G = gts[t];
            p = (G.x <= cx1 && G.z >= cx0 && G.y <= cy1 && G.w >= cy0);
        }
        unsigned bl = __ballot_sync(0xffffffffu, p);
        int wid = t >> 5, lane = t & 31;
        int rank = __popc(bl & ((1u << lane) - 1u));
        if (lane == 0) s1[wid] = __popc(bl);
        __syncthreads();
        int gbase = 0;
        for (int w = 0; w < wid; w++) gbase += s1[w];
        if (p) g_gtlist[b * MAXM + gbase + rank] = t;
        if (t == 0) {
            int tot = 0;
            for (int w = 0; w < TPB / 32; w++) tot += s1[w];
            g_gtcnt[b] = tot;
        }
    }
    __syncthreads();
    g_blockhist[t * nb + b] = h[t];

    // ---------- arrive; last block builds offsets + worklist ----------
    __threadfence();
    __shared__ unsigned old;
    if (t == 0) old = atomicAdd(&g_bar1, 1u);
    __syncthreads();
    if (old == gridDim.x - 1) {
        // In-place per-cell exclusive scan over block counts (row t).
        int run = 0;
        int* row = &g_blockhist[t * nb];
        for (int k = 0; k < nb; k++) {
            int v = __ldcg(&row[k]);
            row[k] = run;
            run += v;
        }
        const int v = run;                        // cell total
        const int mygt = __ldcg(&g_gtcnt[t]);     // written by other blocks (fenced)
        // Bin offsets.
        s1[t] = v; __syncthreads();
        for (int d = 1; d < NCELL; d <<= 1) {
            int x = (t >= d) ? s1[t - d] : 0; __syncthreads();
            s1[t] += x; __syncthreads();
        }
        int excl = s1[t] - v;
        g_offs[t] = excl;
        // Total pairs P.
        __syncthreads();
        s2[t] = v * mygt; __syncthreads();
        for (int d = 1; d < NCELL; d <<= 1) {
            int x = (t >= d) ? s2[t - d] : 0; __syncthreads();
            s2[t] += x; __syncthreads();
        }
        const int P = s2[NCELL - 1];
        __syncthreads();
        // Equal-pair chunk size: s ~ (P/TARGET)/cnt, round up to x256, cap 1024.
        const int Tp = P / TARGET_CHUNKS + 1;
        int s = CHUNK;
        if (mygt > 0) {
            s = (Tp + mygt - 1) / mygt;
            s = (s + 255) & ~255;
            if (s > CHUNK) s = CHUNK;
        }
        int ch = (s > 0) ? (v + s - 1) / s : 0;
        // LPT rank: cells with more GTs first (ties by cell index).
        s2[t] = mygt; __syncthreads();
        int rank = 0;
        for (int u = 0; u < NCELL; u++) {
            int gu = s2[u];
            if (gu > mygt || (gu == mygt && u < t)) rank++;
        }
        __syncthreads();
        // Chunk-count prefix over LPT order.
        s1[rank] = ch; __syncthreads();
        int cv = s1[t];
        for (int d = 1; d < NCELL; d <<= 1) {
            int x = (t >= d) ? s1[t - d] : 0; __syncthreads();
            s1[t] += x; __syncthreads();
        }
        if (t == NCELL - 1) g_nwork = s1[t];
        __syncthreads();
        s2[t] = s1[t] - cv;
        __syncthreads();
        int chexcl = s2[rank];
        for (int k = 0; k < ch; k++)
            g_work[chexcl + k] = make_int4(t, excl + k * s, min(s, v - k * s), 0);
        __threadfence();
        if (t == 0) atomicExch(&g_go, 1u);        // release
    }

    // ---------- spin until released (all blocks co-resident: safe) ----------
    if (t == 0) {
        while (0u == *(volatile unsigned*)&g_go) __nanosleep(64);
    }
    __syncthreads();
    __threadfence();

    // ---------- phase B: scatter (L1 copies of blockhist/offs are stale) ----------
    __shared__ int cur[NCELL];
    cur[t] = __ldcg(&g_offs[t]) + __ldcg(&g_blockhist[t * nb + b]);
    __syncthreads();
#pragma unroll
    for (int k = 0; k < APT; k++) {
        int i = base + k * TPB + t;
        if (i < n) {
            int c = g_cellid[i];                  // own block's writes: safe
            int pos = atomicAdd(&cur[c], 1);
            g_binned[pos] = i;
        }
    }

    // ---------- reset barrier state for graph replay ----------
    __threadfence();
    if (t == 0) {
        unsigned o2 = atomicAdd(&g_bar2, 1u);
        if (o2 == gridDim.x - 1) {                // all blocks passed the spin
            g_bar1 = 0; g_go = 0; g_bar2 = 0;
        }
    }
}

// ---- k_main: frozen R14 mainloop ----
template <int JM>
__device__ __forceinline__ void run_chunk(
    const float4* __restrict__ anc, float* __restrict__ out,
    int astart, int alen, int cnt, int tid,
    const float4* sgc, const float* sga, const int* sgi,
    unsigned long long* smax, unsigned long long* scas)
{
    float ax1[JM], ay1[JM], ax2[JM], ay2[JM], aar[JM], best[JM];
    int bc[JM], aidx[JM];
    bool act[JM];
#pragma unroll
    for (int j = 0; j < JM; j++) {
        int p = tid + j * TPB;
        act[j] = p < alen;
        aidx[j] = act[j] ? g_binned[astart + p] : 0;
        float4 a = act[j] ? anc[aidx[j]] : make_float4(4e9f, 4e9f, 4e9f, 4e9f);
        ax1[j] = a.x; ay1[j] = a.y; ax2[j] = a.z; ay2[j] = a.w;
        aar[j] = __fmul_rn(__fsub_rn(a.z, a.x), __fsub_rn(a.w, a.y));
        best[j] = 0.f;   // all-zero row -> ref argmax 0
        bc[j] = 0;
    }

    const unsigned* smax_hi = (const unsigned*)smax;
    const unsigned* scas_hi = (const unsigned*)scas;
    const unsigned TENTH = 0x3DCCCCCDu;   // __float_as_uint(0.1f)

    for (int c = 0; c < cnt; c++) {
        float4 G = sgc[c];
        float ga = sga[c];
        unsigned mxh = smax_hi[c * 2 + 1];
        unsigned mh2 = scas_hi[(c * 3 + 2) * 2 + 1];
#pragma unroll
        for (int j = 0; j < JM; j++) {
            float ltx = fmaxf(ax1[j], G.x), lty = fmaxf(ay1[j], G.y);
            float rbx = fminf(ax2[j], G.z), rby = fminf(ay2[j], G.w);
            float wd = fmaxf(__fsub_rn(rbx, ltx), 0.f);
            float ht = fmaxf(__fsub_rn(rby, lty), 0.f);
            float inter = __fmul_rn(wd, ht);
            if (inter > 0.f) {
                float denom = __fsub_rn(__fadd_rn(aar[j], ga), inter);
                float iou = __fdiv_rn(inter, denom);   // IEEE rn = reference
                if (iou > best[j]) { best[j] = iou; bc[j] = c; }
                unsigned ib = __float_as_uint(iou);
                if (ib >= mxh) {
                    unsigned long long key =
                        ((unsigned long long)ib << 32) | (unsigned)(~(unsigned)aidx[j]);
                    atomicMax(&smax[c], key);
                    mxh = smax_hi[c * 2 + 1];
                }
                if (ib > TENTH && ib >= mh2) {         // iou > 0.1 gate
                    unsigned long long key =
                        ((unsigned long long)ib << 32) | (unsigned)(~(unsigned)aidx[j]);
                    cascade_insert(&scas[c * 3], key);
                    mh2 = scas_hi[(c * 3 + 2) * 2 + 1];
                }
            }
        }
    }

#pragma unroll
    for (int j = 0; j < JM; j++) {
        if (act[j]) {
            float r = -2.0f;
            if (best[j] < 0.3f) r = -1.0f;
            if (best[j] > 0.5f) r = (float)sgi[bc[j]];
            out[aidx[j]] = r;
        }
    }
}

__global__ void __launch_bounds__(TPB, 5) k_main(
    const float4* __restrict__ anc, const float4* __restrict__ gts,
    int m, float* __restrict__ out, unsigned long long* __restrict__ gtop)
{
    __shared__ float4 sgc[MAXM];
    __shared__ float sga[MAXM];
    __shared__ int sgi[MAXM];
    __shared__ unsigned long long smax[MAXM];
    __shared__ unsigned long long scas[MAXM * 3];

    const int tid = threadIdx.x;
    const bool active_blk = blockIdx.x < g_nwork;
    if (active_blk) {
        int4 w = g_work[blockIdx.x];
        const int cell = w.x, astart = w.y, alen = w.z;
        const int cnt = g_gtcnt[cell];

        // smax fake-seeded from global (monotone-max: safe; merge skips low==0).
        if (tid < cnt) {
            int gi = g_gtlist[cell * MAXM + tid];
            float4 G = gts[gi];
            sgc[tid] = G;
            sga[tid] = __fmul_rn(__fsub_rn(G.z, G.x), __fsub_rn(G.w, G.y));
            sgi[tid] = gi;
            smax[tid] = __ldcg(&gtop[gi * 4 + 0]) & 0xFFFFFFFF00000000ull;
        }
        for (int i = tid; i < cnt * 3; i += TPB) scas[i] = 0ull;
        __syncthreads();

        const int jmax = (alen + TPB - 1) / TPB;
        switch (jmax) {
            case 1: run_chunk<1>(anc, out, astart, alen, cnt, tid, sgc, sga, sgi, smax, scas); break;
            case 2: run_chunk<2>(anc, out, astart, alen, cnt, tid, sgc, sga, sgi, smax, scas); break;
            case 3: run_chunk<3>(anc, out, astart, alen, cnt, tid, sgc, sga, sgi, smax, scas); break;
            default: run_chunk<4>(anc, out, astart, alen, cnt, tid, sgc, sga, sgi, smax, scas); break;
        }

        __syncthreads();
        const unsigned* gtop_hi = (const unsigned*)gtop;
        for (int i = tid; i < cnt * 4; i += TPB) {
            int g = i >> 2, slot = i & 3;
            int orig = sgi[g];
            unsigned long long v = (slot == 0) ? smax[g] : scas[g * 3 + slot - 1];
            if ((unsigned)v == 0u) continue;           // empty or seed fake
            if (slot == 0) {
                atomicMax(&gtop[orig * 4], v);
            } else {
                unsigned gm = gtop_hi[(orig * 4 + 3) * 2 + 1];
                if ((unsigned)(v >> 32) >= gm) cascade_insert(&gtop[orig * 4 + 1], v);
            }
        }
    }

    // ---- ticket: last-finishing block resolves forced claims ----
    __syncthreads();
    __threadfence();
    __shared__ unsigned old;
    if (tid == 0) old = atomicAdd(&g_tick2, 1u);
    __syncthreads();
    if (old == gridDim.x - 1) {
        int* ea = (int*)scas;
        int* eg = ((int*)scas) + MAXM * 3;
        int* win = (int*)sgc;
        __shared__ int rcnt;
        if (tid == 0) rcnt = 0;
        __syncthreads();
        if (tid < m) {
            unsigned long long s0 = __ldcg(&gtop[tid * 4 + 0]);   // overall max
            unsigned long long s1 = __ldcg(&gtop[tid * 4 + 2]);   // vals[1] (>0.1)
            unsigned long long s2 = __ldcg(&gtop[tid * 4 + 3]);   // vals[2] (>0.1)
            float v0 = __uint_as_float((unsigned)(s0 >> 32));
            float v1 = __uint_as_float((unsigned)(s1 >> 32));
            float v2 = __uint_as_float((unsigned)(s2 >> 32));
            int npos = (v0 > 0.5f) + (v1 > 0.5f) + (v2 > 0.5f);
            bool low = npos < 3;
            // k==0 always claims; empty slot = all-zero row -> ref rank0 = anchor 0.
            int a0 = s0 ? (int)(~(unsigned)s0) : 0;
            int e = atomicAdd(&rcnt, 1); ea[e] = a0; eg[e] = tid;
            if (low) {
                if (s1) { e = atomicAdd(&rcnt, 1); ea[e] = (int)(~(unsigned)s1); eg[e] = tid; }
                if (s2) { e = atomicAdd(&rcnt, 1); ea[e] = (int)(~(unsigned)s2); eg[e] = tid; }
            }
        }
        __syncthreads();
        const int E = rcnt;
        for (int j = tid; j < E; j += TPB) win[j] = -1;
        __syncthreads();
        for (int j = tid; j < E; j += TPB) {
            int aj = ea[j];
            int rep = j;
            for (int k = 0; k < j; k++)
                if (ea[k] == aj) { rep = k; break; }
            atomicMax(&win[rep], eg[j]);
        }
        __syncthreads();
        for (int j = tid; j < E; j += TPB)
            if (win[j] >= 0) out[ea[j]] = (float)win[j];
        if (tid == 0) g_tick2 = 0;
    }
}

extern "C" void kernel_launch(void* const* d_in, const int* in_sizes, int n_in,
                              void* d_out, int out_size)
{
    const float4* anc = (const float4*)d_in[0];
    const float4* gts = (const float4*)d_in[1];
    int n = in_sizes[0] / 4;
    int m = in_sizes[1] / 4;
    float* out = (float*)d_out;

    void* ptop = nullptr;
    cudaGetSymbolAddress(&ptop, g_top);

    int nb = (n + CHUNK - 1) / CHUNK;     // 489 blocks: < 1 wave, spin-safe
    k_prep<<<nb, TPB>>>(anc, gts, n, m, nb);
    int mblocks = NCELL + (n + 255) / 256 + 2;
    k_main<<<mblocks, TPB>>>(anc, gts, m, out, (unsigned long long*)ptop);
}